// round 3
// baseline (speedup 1.0000x reference)
#include <cuda_runtime.h>
#include <math.h>

#define H 1024
#define V 50257
#define S 4096
#define G3H 3072

#define LOGITS_ROWS_PER_BLOCK 8
#define N_LOGIT_BLOCKS ((V + LOGITS_ROWS_PER_BLOCK - 1) / LOGITS_ROWS_PER_BLOCK)  // 6283
#define N_SCORE_BLOCKS (S / 8)   // 512

// ---- scratch (__device__ globals; allocation-free rule) ----
__device__ float g_gi[G3H];
__device__ float g_gh[G3H];
__device__ float g_hnew[H];
__device__ float g_ctx[H];
__device__ float g_scores[S];
__device__ float g_pmax[N_SCORE_BLOCKS];
__device__ float g_psum[N_SCORE_BLOCKS];
__device__ float g_M;        // softmax max
__device__ float g_invS;     // softmax 1/sum
__device__ float g_lmax[N_LOGIT_BLOCKS];
__device__ float g_lsum[N_LOGIT_BLOCKS];
__device__ float g_lse;

__device__ __forceinline__ float warp_sum(float v) {
#pragma unroll
    for (int o = 16; o; o >>= 1) v += __shfl_down_sync(0xffffffffu, v, o);
    return v;
}
__device__ __forceinline__ float warp_max(float v) {
#pragma unroll
    for (int o = 16; o; o >>= 1) v = fmaxf(v, __shfl_down_sync(0xffffffffu, v, o));
    return v;
}
__device__ __forceinline__ float sigmoidf_(float x) { return 1.0f / (1.0f + expf(-x)); }

// ============================================================================
// 1) gates: gi rows (2048-dot) and gh rows (1024-dot), warp per row
// ============================================================================
__global__ void gates_kernel(const int* __restrict__ word,
                             const float* __restrict__ last_context,
                             const float* __restrict__ last_hidden,
                             const float* __restrict__ emb_tab,
                             const float* __restrict__ w_ih,
                             const float* __restrict__ w_hh,
                             const float* __restrict__ b_ih,
                             const float* __restrict__ b_hh) {
    int warp = (blockIdx.x * blockDim.x + threadIdx.x) >> 5;
    int lane = threadIdx.x & 31;

    if (warp < G3H) {
        const float4* wr   = (const float4*)(w_ih + (size_t)warp * (2 * H));
        const float4* embr = (const float4*)(emb_tab + (size_t)word[0] * H);
        const float4* lc4  = (const float4*)last_context;
        float acc = 0.f;
#pragma unroll
        for (int k = 0; k < 16; k++) {
            int j = lane + k * 32;
            float4 w4 = wr[j];
            float4 x4 = (j < 256) ? embr[j] : lc4[j - 256];
            acc += w4.x * x4.x + w4.y * x4.y + w4.z * x4.z + w4.w * x4.w;
        }
        acc = warp_sum(acc);
        if (lane == 0) g_gi[warp] = acc + b_ih[warp];
    } else if (warp < 2 * G3H) {
        int r = warp - G3H;
        const float4* wr = (const float4*)(w_hh + (size_t)r * H);
        const float4* h4 = (const float4*)last_hidden;
        float acc = 0.f;
#pragma unroll
        for (int k = 0; k < 8; k++) {
            int j = lane + k * 32;
            float4 w4 = wr[j];
            float4 x4 = h4[j];
            acc += w4.x * x4.x + w4.y * x4.y + w4.z * x4.z + w4.w * x4.w;
        }
        acc = warp_sum(acc);
        if (lane == 0) g_gh[r] = acc + b_hh[r];
    }
}

// ============================================================================
// 2) GRU combine -> h_new; also zero g_ctx (per-replay reinit)
// ============================================================================
__global__ void gru_kernel(const float* __restrict__ last_hidden,
                           float* __restrict__ out) {
    int d = threadIdx.x;
    float r = sigmoidf_(g_gi[d]       + g_gh[d]);
    float z = sigmoidf_(g_gi[d + H]   + g_gh[d + H]);
    float n = tanhf    (g_gi[d + 2*H] + r * g_gh[d + 2*H]);
    float h = last_hidden[d];
    float hn = (1.0f - z) * n + z * h;
    g_hnew[d] = hn;
    g_ctx[d]  = 0.0f;
    out[V + H + d] = hn;     // h_new output slot
}

// ============================================================================
// 3) scores + per-block softmax partials (8 warps = 8 rows per block)
// ============================================================================
__global__ void scores_kernel(const float* __restrict__ enc) {
    __shared__ float sc[8];
    int wid  = threadIdx.x >> 5;
    int lane = threadIdx.x & 31;
    int row  = blockIdx.x * 8 + wid;

    const float4* e4 = (const float4*)(enc + (size_t)row * H);
    const float4* h4 = (const float4*)g_hnew;
    float acc = 0.f;
#pragma unroll
    for (int k = 0; k < 8; k++) {
        int j = lane + k * 32;
        float4 a = e4[j], b = h4[j];
        acc += a.x * b.x + a.y * b.y + a.z * b.z + a.w * b.w;
    }
    acc = warp_sum(acc);
    if (lane == 0) { g_scores[row] = acc; sc[wid] = acc; }
    __syncthreads();
    if (threadIdx.x == 0) {
        float m = sc[0];
#pragma unroll
        for (int i = 1; i < 8; i++) m = fmaxf(m, sc[i]);
        float s = 0.f;
#pragma unroll
        for (int i = 0; i < 8; i++) s += expf(sc[i] - m);
        g_pmax[blockIdx.x] = m;
        g_psum[blockIdx.x] = s;
    }
}

// ============================================================================
// 4) combine softmax partials (1 block, 512 threads, 512 partials)
// ============================================================================
__global__ void softmax_combine_kernel() {
    __shared__ float red[32];
    int tid = threadIdx.x;
    float m = g_pmax[tid];
    float mm = warp_max(m);
    if ((tid & 31) == 0) red[tid >> 5] = mm;
    __syncthreads();
    if (tid < 32) {
        float t = (tid < 16) ? red[tid] : -1e30f;
        t = warp_max(t);
        if (tid == 0) red[0] = t;
    }
    __syncthreads();
    float M = red[0];
    __syncthreads();
    float s = g_psum[tid] * expf(m - M);
    s = warp_sum(s);
    if ((tid & 31) == 0) red[tid >> 5] = s;
    __syncthreads();
    if (tid < 32) {
        float t = (tid < 16) ? red[tid] : 0.f;
        t = warp_sum(t);
        if (tid == 0) { g_M = M; g_invS = 1.0f / t; }
    }
}

// ============================================================================
// 5) context = attn @ enc; normalize on the fly; bx==0 writes attn output
// ============================================================================
__global__ void context_kernel(const float* __restrict__ enc,
                               float* __restrict__ attn_out) {
    __shared__ float a_sh[128];
    int s0 = blockIdx.y * 128;
    int d  = blockIdx.x * 128 + threadIdx.x;
    float M = g_M, invS = g_invS;
    float a = expf(g_scores[s0 + threadIdx.x] - M) * invS;
    a_sh[threadIdx.x] = a;
    if (blockIdx.x == 0) attn_out[s0 + threadIdx.x] = a;
    __syncthreads();
    float acc = 0.f;
#pragma unroll 4
    for (int i = 0; i < 128; i++)
        acc += a_sh[i] * enc[(size_t)(s0 + i) * H + d];
    atomicAdd(&g_ctx[d], acc);
}

// ============================================================================
// 6) logits (warp per row) + per-block log-softmax partials
// ============================================================================
__global__ void logits_kernel(const float* __restrict__ out_w,
                              const float* __restrict__ out_b,
                              float* __restrict__ logits) {
    __shared__ float4 x4[512];
    __shared__ float lg[LOGITS_ROWS_PER_BLOCK];
    float* xs = (float*)x4;
    for (int i = threadIdx.x; i < H; i += blockDim.x) {
        xs[i]     = g_hnew[i];
        xs[H + i] = g_ctx[i];
    }
    __syncthreads();

    int wid  = threadIdx.x >> 5;
    int lane = threadIdx.x & 31;
    int row  = blockIdx.x * LOGITS_ROWS_PER_BLOCK + wid;

    float logit = -1e30f;
    if (row < V) {
        const float4* wr = (const float4*)(out_w + (size_t)row * (2 * H));
        float acc = 0.f;
#pragma unroll
        for (int k = 0; k < 16; k++) {
            int j = lane + k * 32;
            float4 w4 = wr[j];
            float4 v4 = x4[j];
            acc += w4.x * v4.x + w4.y * v4.y + w4.z * v4.z + w4.w * v4.w;
        }
        acc = warp_sum(acc);
        if (lane == 0) {
            logit = acc + out_b[row];
            logits[row] = logit;
        }
    }
    if (lane == 0) lg[wid] = logit;
    __syncthreads();
    if (threadIdx.x == 0) {
        float m = lg[0];
#pragma unroll
        for (int i = 1; i < LOGITS_ROWS_PER_BLOCK; i++) m = fmaxf(m, lg[i]);
        float s = 0.f;
#pragma unroll
        for (int i = 0; i < LOGITS_ROWS_PER_BLOCK; i++) s += expf(lg[i] - m);
        g_lmax[blockIdx.x] = m;
        g_lsum[blockIdx.x] = s;
    }
}

// ============================================================================
// 7) combine lse partials (1 block, 1024 thr over 6283) + write context out
// ============================================================================
__global__ void lse_combine_kernel(float* __restrict__ out) {
    __shared__ float red[32];
    int tid = threadIdx.x;

    float m = -1e30f;
    for (int i = tid; i < N_LOGIT_BLOCKS; i += 1024) m = fmaxf(m, g_lmax[i]);
    float mm = warp_max(m);
    if ((tid & 31) == 0) red[tid >> 5] = mm;
    __syncthreads();
    if (tid < 32) {
        float t = red[tid];
        t = warp_max(t);
        if (tid == 0) red[0] = t;
    }
    __syncthreads();
    float M = red[0];
    __syncthreads();

    float s = 0.f;
    for (int i = tid; i < N_LOGIT_BLOCKS; i += 1024) s += g_lsum[i] * expf(g_lmax[i] - M);
    s = warp_sum(s);
    if ((tid & 31) == 0) red[tid >> 5] = s;
    __syncthreads();
    if (tid < 32) {
        float t = red[tid];
        t = warp_sum(t);
        if (tid == 0) g_lse = M + logf(t);
    }

    // piggyback: context output slot
    out[V + tid] = g_ctx[tid];
}

// ============================================================================
// 8) subtract lse across V (wide grid)
// ============================================================================
__global__ void subtract_kernel(float* __restrict__ out) {
    int i = blockIdx.x * blockDim.x + threadIdx.x;
    if (i < V) out[i] -= g_lse;
}

// ============================================================================
extern "C" void kernel_launch(void* const* d_in, const int* in_sizes, int n_in,
                              void* d_out, int out_size) {
    const int*   word  = (const int*)  d_in[0];
    const float* lc    = (const float*)d_in[1];
    const float* lh    = (const float*)d_in[2];
    const float* enc   = (const float*)d_in[3];
    const float* emb   = (const float*)d_in[4];
    const float* w_ih  = (const float*)d_in[5];
    const float* w_hh  = (const float*)d_in[6];
    const float* b_ih  = (const float*)d_in[7];
    const float* b_hh  = (const float*)d_in[8];
    const float* out_w = (const float*)d_in[9];
    const float* out_b = (const float*)d_in[10];
    float* out = (float*)d_out;

    float* attn_slot = out + V + 2 * H;

    gates_kernel<<<768, 256>>>(word, lc, lh, emb, w_ih, w_hh, b_ih, b_hh);
    gru_kernel<<<1, 1024>>>(lh, out);
    scores_kernel<<<N_SCORE_BLOCKS, 256>>>(enc);
    softmax_combine_kernel<<<1, 512>>>();
    {
        dim3 g(H / 128, S / 128);
        context_kernel<<<g, 128>>>(enc, attn_slot);
    }
    logits_kernel<<<N_LOGIT_BLOCKS, 256>>>(out_w, out_b, out);
    lse_combine_kernel<<<1, 1024>>>(out);
    subtract_kernel<<<(V + 255) / 256, 256>>>(out);
}